// round 1
// baseline (speedup 1.0000x reference)
#include <cuda_runtime.h>
#include <math.h>

#define NS 4096
#define NT 4096
#define N_INT ((double)(NS-2)*(double)(NT-2))

// accumulators: [0]=pde sum, [1]=bc sum, [2]=tc sum
__device__ double g_acc[3];

__global__ void zero_acc_kernel() {
    if (threadIdx.x < 3) g_acc[threadIdx.x] = 0.0;
}

__inline__ __device__ float warp_reduce(float v) {
    #pragma unroll
    for (int o = 16; o > 0; o >>= 1) v += __shfl_down_sync(0xffffffffu, v, o);
    return v;
}

__global__ __launch_bounds__(256)
void loss_kernel(const float* __restrict__ V,
                 float c1f, float c2f, float su_coef, float suu_coef,
                 float inv2dt)
{
    const int tid = threadIdx.x;
    const int bid = blockIdx.x;
    __shared__ float sred[8];
    __shared__ float sred2[8];

    if (bid < NS - 2) {
        // ---- PDE residual over interior row i = bid+1 ----
        const int i = bid + 1;
        const float u   = (float)i * (1.0f / 4095.0f);
        const float L   = c2f * u + c1f * (1.0f - u);
        const float S   = 100.0f + 30.0f * (L * L * L / 6.0f + L);
        const float Sn  = S / 300.0f;
        const float Su  = su_coef * (0.5f * L * L + 1.0f);
        const float Sun = Su / 300.0f;
        const float Suun = (suu_coef * L) / 300.0f;
        const float invSun  = 1.0f / Sun;
        const float invSun3 = 1.0f / (Sun * Sun * Sun);
        const float aSn = 2.5f * Sn;          // ALPHA * S_norm
        const float Sn2 = Sn * Sn;

        const float4* __restrict__ rm = (const float4*)(V + (size_t)(i - 1) * NT);
        const float4* __restrict__ r0 = (const float4*)(V + (size_t)(i)     * NT);
        const float4* __restrict__ rp = (const float4*)(V + (size_t)(i + 1) * NT);
        const float*  __restrict__ row0 = V + (size_t)i * NT;

        const float inv2du  = 2047.5f;        // 1/(2*DU), DU = 1/4095
        const float invdu2  = 16769025.0f;    // 4095^2 (exact in fp32)

        float part = 0.0f;
        #pragma unroll
        for (int k = tid; k < NT / 4; k += 256) {
            float4 a = rm[k];
            float4 b = r0[k];
            float4 c = rp[k];
            const int j0 = 4 * k;
            const float left  = row0[j0 == 0 ? 0 : j0 - 1];
            const float right = row0[j0 + 4 >= NT ? NT - 1 : j0 + 4];

            float vm[4] = {a.x, a.y, a.z, a.w};
            float vc[6] = {left, b.x, b.y, b.z, b.w, right};
            float vp[4] = {c.x, c.y, c.z, c.w};

            #pragma unroll
            for (int e = 0; e < 4; e++) {
                const int j = j0 + e;
                const float v0  = vc[e + 1];
                const float Vu  = (vp[e] - vm[e]) * inv2du;
                const float Vuu = (vp[e] - 2.0f * v0 + vm[e]) * invdu2;
                const float Vt  = (vc[e + 2] - vc[e]) * inv2dt;
                const float VS  = Vu * invSun;
                float VSS = (Vuu * Sun - Vu * Suun) * invSun3;
                VSS = fminf(fmaxf(VSS, -100.0f), 100.0f);
                const float res = Vt - Sn2 * VSS - aSn * VS + 2.5f * v0;
                if (j >= 1 && j <= NT - 2) part += res * res;
            }
        }

        // block reduce -> atomic
        part = warp_reduce(part);
        if ((tid & 31) == 0) sred[tid >> 5] = part;
        __syncthreads();
        if (tid < 32) {
            float v = (tid < 8) ? sred[tid] : 0.0f;
            v = warp_reduce(v);
            if (tid == 0) atomicAdd(&g_acc[0], (double)v);
        }
    } else {
        // ---- BC at S=S_max (last row) and terminal condition (last column) ----
        float pb = 0.0f, pt = 0.0f;
        const float* lastrow = V + (size_t)(NS - 1) * NT;
        for (int j = tid; j < NT; j += 256) {
            const float t   = (float)j * (1.0f / 4095.0f);
            const float tgt = 1.0f - 100.0f * __expf(0.0f) * 0.0f -  // placeholder avoid fuse
                              0.0f;
            (void)tgt;
            const float target = 1.0f - (100.0f * expf(-0.05f * (1.0f - t))) / 300.0f;
            const float d = lastrow[j] - target;
            pb += d * d;
        }
        for (int i2 = tid; i2 < NS; i2 += 256) {
            const float u = (float)i2 * (1.0f / 4095.0f);
            const float x = 50.0f * (u - 0.33333334f);   // K/S_MAX in fp32
            const float sp = (fmaxf(x, 0.0f) + log1pf(expf(-fabsf(x)))) / 50.0f;
            const float d  = V[(size_t)i2 * NT + (NT - 1)] - sp;
            const float ad = fabsf(d);
            pt += (ad < 0.01f) ? 0.5f * d * d : 0.01f * (ad - 0.005f);
        }
        pb = warp_reduce(pb);
        pt = warp_reduce(pt);
        if ((tid & 31) == 0) { sred[tid >> 5] = pb; sred2[tid >> 5] = pt; }
        __syncthreads();
        if (tid < 32) {
            float vb = (tid < 8) ? sred[tid]  : 0.0f;
            float vt = (tid < 8) ? sred2[tid] : 0.0f;
            vb = warp_reduce(vb);
            vt = warp_reduce(vt);
            if (tid == 0) {
                atomicAdd(&g_acc[1], (double)vb);
                atomicAdd(&g_acc[2], (double)vt);
            }
        }
    }
}

__global__ void finalize_kernel(float* out) {
    const double pde = g_acc[0] / N_INT;
    const double bc  = g_acc[1] / (double)NT;
    const double tc  = g_acc[2] / (double)NS;
    out[0] = (float)(pde + 10.0 * bc + 10.0 * tc);
}

static double solve_depressed_cubic(double Q) {
    const double p = 6.0;             // CHI
    const double q = 6.0 * Q;
    const double sp = sqrt(p);
    double arg = fabs(q) / (2.0 * p * sp / (3.0 * sqrt(3.0)));
    if (arg < 1.0) arg = 1.0;
    const double c = 2.0 * sp * cosh(acosh(arg) / 3.0);
    return (q >= 0.0) ? -c : c;
}

extern "C" void kernel_launch(void* const* d_in, const int* in_sizes, int n_in,
                              void* d_out, int out_size)
{
    const float* V = (const float*)d_in[0];
    float* out = (float*)d_out;

    // host-side (pure CPU math, capture-safe) stretching constants
    const double C1 = solve_depressed_cubic((100.0 - 0.0) / 30.0);
    const double C2 = solve_depressed_cubic((100.0 - 300.0) / 30.0);
    const double dL = C2 - C1;
    const float c1f = (float)C1;
    const float c2f = (float)C2;
    const float su_coef  = (float)(30.0 * dL);        // ALPHA_STR * dL
    const float suu_coef = (float)(30.0 * dL * dL);   // ALPHA_STR * dL^2
    const double TAU_MAX = 0.5 * 0.2 * 0.2 * 1.0;     // 0.02
    const double DT_NORM = TAU_MAX / (double)(NT - 1);
    const float inv2dt = (float)(1.0 / (2.0 * DT_NORM));

    zero_acc_kernel<<<1, 32>>>();
    loss_kernel<<<NS - 2 + 1, 256>>>(V, c1f, c2f, su_coef, suu_coef, inv2dt);
    finalize_kernel<<<1, 1>>>(out);
}

// round 2
// speedup vs baseline: 1.0981x; 1.0981x over previous
#include <cuda_runtime.h>
#include <math.h>

#define NS 4096
#define NT 4096
#define RPB 32                  // rows per PDE block
#define NCOLB 2                 // column blocks (2048 cols each)
#define NROWB 128               // row chunks
#define NPDE (NCOLB * NROWB)    // 256 PDE blocks
#define GRID (NPDE + 1)         // +1 BC/TC block
#define N_INT ((double)(NS - 2) * (double)(NT - 2))

__device__ float g_part[NPDE + 2];
__device__ unsigned int g_count = 0;

__inline__ __device__ float warp_reduce(float v) {
    #pragma unroll
    for (int o = 16; o > 0; o >>= 1) v += __shfl_down_sync(0xffffffffu, v, o);
    return v;
}
__inline__ __device__ double warp_reduce_d(double v) {
    #pragma unroll
    for (int o = 16; o > 0; o >>= 1) v += __shfl_down_sync(0xffffffffu, v, o);
    return v;
}

// Residual^2 contribution of one grid row i (center row = b), 4 columns starting at jb.
__device__ __forceinline__ float row_res(int i, int jb, const float* __restrict__ V,
                                         const float4 a, const float4 b, const float4 c,
                                         float c1f, float c2f, float su_coef,
                                         float suu_coef, float inv2dt)
{
    const float u    = (float)i * (1.0f / 4095.0f);
    const float L    = c2f * u + c1f * (1.0f - u);
    const float S    = 100.0f + 30.0f * (L * L * L * (1.0f / 6.0f) + L);
    const float Sn   = S * (1.0f / 300.0f);
    const float Sun  = su_coef * (0.5f * L * L + 1.0f) * (1.0f / 300.0f);
    const float Suun = (suu_coef * L) * (1.0f / 300.0f);
    const float invSun  = 1.0f / Sun;
    const float invSun3 = 1.0f / (Sun * Sun * Sun);
    const float aSn  = 2.5f * Sn;
    const float Sn2  = Sn * Sn;
    const float inv2du = 2047.5f;        // 1/(2*DU), DU = 1/4095
    const float invdu2 = 16769025.0f;    // 4095^2

    const float* __restrict__ row = V + (size_t)i * NT;
    const float left  = __ldg(row + (jb == 0 ? 0 : jb - 1));
    const float right = __ldg(row + (jb + 4 >= NT ? NT - 1 : jb + 4));

    const float vm[4] = {a.x, a.y, a.z, a.w};
    const float vc[6] = {left, b.x, b.y, b.z, b.w, right};
    const float vp[4] = {c.x, c.y, c.z, c.w};

    float part = 0.0f;
    #pragma unroll
    for (int e = 0; e < 4; e++) {
        const int j = jb + e;
        const float v0  = vc[e + 1];
        const float Vu  = (vp[e] - vm[e]) * inv2du;
        const float Vuu = (vp[e] - 2.0f * v0 + vm[e]) * invdu2;
        const float Vt  = (vc[e + 2] - vc[e]) * inv2dt;
        const float VS  = Vu * invSun;
        float VSS = (Vuu * Sun - Vu * Suun) * invSun3;
        VSS = fminf(fmaxf(VSS, -100.0f), 100.0f);
        const float res = Vt - Sn2 * VSS - aSn * VS + 2.5f * v0;
        if (j >= 1 && j <= NT - 2) part += res * res;
    }
    return part;
}

__global__ void __launch_bounds__(512, 2)
loss_kernel(const float* __restrict__ V, float* __restrict__ out,
            float c1f, float c2f, float su_coef, float suu_coef, float inv2dt)
{
    const int tid = threadIdx.x;
    const int bid = blockIdx.x;
    __shared__ float s1[16];
    __shared__ float s2[16];
    __shared__ unsigned s_old;

    if (bid < NPDE) {
        // ---- PDE residual over rows [i0, ie], columns [jb, jb+4) ----
        const int cb = bid & (NCOLB - 1);
        const int rc = bid >> 1;
        const int jb = (cb * 512 + tid) * 4;
        const int i0 = 1 + rc * RPB;
        const int ie = min(i0 + RPB - 1, NS - 2);   // inclusive

        float4 vm = *(const float4*)(V + (size_t)(i0 - 1) * NT + jb);
        float4 vc = *(const float4*)(V + (size_t)i0 * NT + jb);
        float part = 0.0f;
        int i = i0;
        for (; i + 3 <= ie; i += 4) {
            const float4 p0 = *(const float4*)(V + (size_t)(i + 1) * NT + jb);
            const float4 p1 = *(const float4*)(V + (size_t)(i + 2) * NT + jb);
            const float4 p2 = *(const float4*)(V + (size_t)(i + 3) * NT + jb);
            const float4 p3 = *(const float4*)(V + (size_t)(i + 4) * NT + jb);
            part += row_res(i,     jb, V, vm, vc, p0, c1f, c2f, su_coef, suu_coef, inv2dt);
            part += row_res(i + 1, jb, V, vc, p0, p1, c1f, c2f, su_coef, suu_coef, inv2dt);
            part += row_res(i + 2, jb, V, p0, p1, p2, c1f, c2f, su_coef, suu_coef, inv2dt);
            part += row_res(i + 3, jb, V, p1, p2, p3, c1f, c2f, su_coef, suu_coef, inv2dt);
            vm = p2; vc = p3;
        }
        for (; i <= ie; i++) {
            const float4 p0 = *(const float4*)(V + (size_t)(i + 1) * NT + jb);
            part += row_res(i, jb, V, vm, vc, p0, c1f, c2f, su_coef, suu_coef, inv2dt);
            vm = vc; vc = p0;
        }

        part = warp_reduce(part);
        if ((tid & 31) == 0) s1[tid >> 5] = part;
        __syncthreads();
        if (tid < 32) {
            float v = (tid < 16) ? s1[tid] : 0.0f;
            v = warp_reduce(v);
            if (tid == 0) g_part[bid] = v;
        }
    } else {
        // ---- BC at S=S_max (last row) and terminal condition (last column) ----
        float pb = 0.0f, pt = 0.0f;
        const float* lastrow = V + (size_t)(NS - 1) * NT;
        for (int j = tid; j < NT; j += 512) {
            const float t = (float)j * (1.0f / 4095.0f);
            const float target = 1.0f - (100.0f * expf(-0.05f * (1.0f - t))) * (1.0f / 300.0f);
            const float d = lastrow[j] - target;
            pb += d * d;
        }
        for (int i2 = tid; i2 < NS; i2 += 512) {
            const float u = (float)i2 * (1.0f / 4095.0f);
            const float x = 50.0f * (u - 0.33333334f);   // K/S_MAX in fp32
            const float sp = (fmaxf(x, 0.0f) + log1pf(expf(-fabsf(x)))) * (1.0f / 50.0f);
            const float d = V[(size_t)i2 * NT + (NT - 1)] - sp;
            const float ad = fabsf(d);
            pt += (ad < 0.01f) ? 0.5f * d * d : 0.01f * (ad - 0.005f);
        }
        pb = warp_reduce(pb);
        pt = warp_reduce(pt);
        if ((tid & 31) == 0) { s1[tid >> 5] = pb; s2[tid >> 5] = pt; }
        __syncthreads();
        if (tid < 32) {
            float vb = (tid < 16) ? s1[tid] : 0.0f;
            float vt = (tid < 16) ? s2[tid] : 0.0f;
            vb = warp_reduce(vb);
            vt = warp_reduce(vt);
            if (tid == 0) { g_part[NPDE] = vb; g_part[NPDE + 1] = vt; }
        }
    }

    // ---- last block to finish does the final weighted reduce ----
    if (tid == 0) {
        __threadfence();
        s_old = atomicAdd(&g_count, 1u);
    }
    __syncthreads();
    if (s_old == GRID - 1) {
        __threadfence();
        double w = 0.0;
        if (tid < NPDE)            w = (double)g_part[tid] / N_INT;
        else if (tid == NPDE)      w = 10.0 * (double)g_part[NPDE] / (double)NT;
        else if (tid == NPDE + 1)  w = 10.0 * (double)g_part[NPDE + 1] / (double)NS;

        __shared__ double sd[16];
        double v = warp_reduce_d(w);
        if ((tid & 31) == 0) sd[tid >> 5] = v;
        __syncthreads();
        if (tid < 32) {
            double t2 = (tid < 16) ? sd[tid] : 0.0;
            t2 = warp_reduce_d(t2);
            if (tid == 0) {
                out[0] = (float)t2;
                g_count = 0;    // self-reset for next replay (deterministic)
            }
        }
    }
}

static double solve_depressed_cubic(double Q) {
    const double p = 6.0;             // CHI
    const double q = 6.0 * Q;
    const double sp = sqrt(p);
    double arg = fabs(q) / (2.0 * p * sp / (3.0 * sqrt(3.0)));
    if (arg < 1.0) arg = 1.0;
    const double c = 2.0 * sp * cosh(acosh(arg) / 3.0);
    return (q >= 0.0) ? -c : c;
}

extern "C" void kernel_launch(void* const* d_in, const int* in_sizes, int n_in,
                              void* d_out, int out_size)
{
    const float* V = (const float*)d_in[0];
    float* out = (float*)d_out;

    const double C1 = solve_depressed_cubic((100.0 - 0.0) / 30.0);
    const double C2 = solve_depressed_cubic((100.0 - 300.0) / 30.0);
    const double dL = C2 - C1;
    const float c1f = (float)C1;
    const float c2f = (float)C2;
    const float su_coef  = (float)(30.0 * dL);        // ALPHA_STR * dL
    const float suu_coef = (float)(30.0 * dL * dL);   // ALPHA_STR * dL^2
    const double TAU_MAX = 0.5 * 0.2 * 0.2 * 1.0;     // 0.02
    const double DT_NORM = TAU_MAX / (double)(NT - 1);
    const float inv2dt = (float)(1.0 / (2.0 * DT_NORM));

    loss_kernel<<<GRID, 512>>>(V, out, c1f, c2f, su_coef, suu_coef, inv2dt);
}

// round 3
// speedup vs baseline: 1.5878x; 1.4459x over previous
#include <cuda_runtime.h>
#include <math.h>

#define NS 4096
#define NT 4096
#define NPDE 296                 // 148 row-chunks x 2 col-halves = exactly 2 blocks/SM
#define W_PDE (1.0 / (4094.0 * 4094.0))
#define W_EDGE_F ((float)(10.0 / 4096.0))

__device__ double g_part[NPDE];
__device__ unsigned int g_count = 0;

__inline__ __device__ float warp_reduce(float v) {
    #pragma unroll
    for (int o = 16; o > 0; o >>= 1) v += __shfl_down_sync(0xffffffffu, v, o);
    return v;
}
__inline__ __device__ double warp_reduce_d(double v) {
    #pragma unroll
    for (int o = 16; o > 0; o >>= 1) v += __shfl_down_sync(0xffffffffu, v, o);
    return v;
}

// One stencil row: 4 elements. cstv = {A1, A2, H, A3} for this row.
__device__ __forceinline__ void accum_row(const float4 cstv,
                                          const float4 vm, const float4 vc, const float4 vp,
                                          float left, float right,
                                          float m0, float m3, float inv2dt, float& part)
{
    const float A1 = cstv.x, A2 = cstv.y, H = cstv.z, A3 = cstv.w;
    const float vls[6] = {left, vc.x, vc.y, vc.z, vc.w, right};
    const float vmm[4] = {vm.x, vm.y, vm.z, vm.w};
    const float vpp[4] = {vp.x, vp.y, vp.z, vp.w};
    #pragma unroll
    for (int e = 0; e < 4; e++) {
        const float v0   = vls[e + 1];
        const float s    = vpp[e] + vmm[e];
        const float Vuu  = fmaf(-2.0f, v0, s);          // raw 2nd diff (unscaled)
        const float Vu   = vpp[e] - vmm[e];             // raw 1st diff (unscaled)
        const float raw  = fmaf(Vuu, A1, -(Vu * A2));   // = Sn^2 * VSS (unclipped)
        const float t2c  = fminf(fmaxf(raw, -H), H);    // = Sn^2 * clip(VSS, +-100)
        const float dvc  = vls[e + 2] - vls[e];
        float t = fmaf(dvc, inv2dt, -t2c);              // Vt - Sn^2*VSS
        t = fmaf(-A3, Vu, t);                           // - alpha*Sn*VS
        const float res = fmaf(2.5f, v0, t);            // + alpha*V
        const float r2  = res * res;
        const float m = (e == 0) ? m0 : ((e == 3) ? m3 : 1.0f);
        part = fmaf(r2, m, part);
    }
}

__global__ void __launch_bounds__(512, 2)
loss_kernel(const float* __restrict__ V, float* __restrict__ out,
            float c1f, float c2f, float su_coef, float suu_coef, float inv2dt)
{
    const int tid = threadIdx.x;
    const int bid = blockIdx.x;
    const int rc  = bid >> 1;          // row chunk 0..147
    const int cb  = bid & 1;           // column half

    __shared__ float4 cst[28];
    __shared__ float s1[16], s2[16];
    __shared__ unsigned s_old;

    // balanced rows: chunks 0..97 get 28 rows, 98..147 get 27 (total 4094)
    const int i0    = 1 + rc * 27 + min(rc, 98);
    const int nrows = 27 + (rc < 98 ? 1 : 0);

    // ---- per-row folded constants into shared ----
    if (tid < nrows) {
        const int   i  = i0 + tid;
        const float u  = (float)i * (1.0f / 4095.0f);
        const float L  = c2f * u + c1f * (1.0f - u);
        const float S  = 100.0f + 30.0f * (L * L * L * (1.0f / 6.0f) + L);
        const float Sn = S * (1.0f / 300.0f);
        const float Sun  = su_coef * (0.5f * L * L + 1.0f) * (1.0f / 300.0f);
        const float Suun = (suu_coef * L) * (1.0f / 300.0f);
        const float invSun  = 1.0f / Sun;
        const float invSun2 = invSun * invSun;
        const float Sn2 = Sn * Sn;
        float4 cc;
        cc.x = 16769025.0f * Sn2 * invSun2;                 // A1 = Sn^2/(du^2 Sun^2)
        cc.y = 2047.5f * Suun * Sn2 * invSun2 * invSun;     // A2 = Suun Sn^2/(2du Sun^3)
        cc.z = 100.0f * Sn2;                                // clamp bound H
        cc.w = 2.5f * Sn * 2047.5f * invSun;                // A3 = alpha Sn/(2du Sun)
        cst[tid] = cc;
    }

    // ---- distributed BC/TC edge losses (pre-weighted), ~28 elems/block ----
    float edge = 0.0f;
    {
        const int g = bid * 28 + tid;
        if (tid < 28 && g < 2 * NT) {
            if (g < NT) {
                const float t = (float)g * (1.0f / 4095.0f);
                const float target = 1.0f - (100.0f * expf(-0.05f * (1.0f - t))) * (1.0f / 300.0f);
                const float d = V[(size_t)(NS - 1) * NT + g] - target;
                edge = W_EDGE_F * (d * d);
            } else {
                const int   i2 = g - NT;
                const float u  = (float)i2 * (1.0f / 4095.0f);
                const float x  = 50.0f * (u - 0.33333334f);
                const float sp = (fmaxf(x, 0.0f) + log1pf(expf(-fabsf(x)))) * (1.0f / 50.0f);
                const float d  = V[(size_t)i2 * NT + (NT - 1)] - sp;
                const float ad = fabsf(d);
                const float h  = (ad < 0.01f) ? 0.5f * d * d : 0.01f * (ad - 0.005f);
                edge = W_EDGE_F * h;
            }
        }
    }
    __syncthreads();

    // ---- PDE residual, rolling 3-row register stencil, 4-row unroll ----
    const int   jb   = (cb * 512 + tid) * 4;
    const int   offL = (jb == 0) ? 0 : jb - 1;
    const int   offR = (jb == 4092) ? 4095 : jb + 4;
    const float m0   = (jb == 0) ? 0.0f : 1.0f;
    const float m3   = (jb == 4092) ? 0.0f : 1.0f;

    const float* base = V + (size_t)(i0 - 1) * NT + jb;  // row i0-1 at this thread's cols
    const float* crow = V + (size_t)i0 * NT;             // center-row base for edge scalars
    float4 vm = *(const float4*)base;
    float4 vc = *(const float4*)(base + NT);

    float part = 0.0f;
    int r = 0;
    for (; r + 4 <= nrows; r += 4) {
        const float* p = base + (size_t)(r + 2) * NT;
        const float4 p0 = *(const float4*)(p);
        const float4 p1 = *(const float4*)(p + NT);
        const float4 p2 = *(const float4*)(p + 2 * NT);
        const float4 p3 = *(const float4*)(p + 3 * NT);
        const float* c0 = crow + (size_t)r * NT;
        accum_row(cst[r],     vm, vc, p0, c0[offL],          c0[offR],          m0, m3, inv2dt, part);
        accum_row(cst[r + 1], vc, p0, p1, c0[NT + offL],     c0[NT + offR],     m0, m3, inv2dt, part);
        accum_row(cst[r + 2], p0, p1, p2, c0[2 * NT + offL], c0[2 * NT + offR], m0, m3, inv2dt, part);
        accum_row(cst[r + 3], p1, p2, p3, c0[3 * NT + offL], c0[3 * NT + offR], m0, m3, inv2dt, part);
        vm = p2; vc = p3;
    }
    for (; r < nrows; r++) {
        const float4 p0 = *(const float4*)(base + (size_t)(r + 2) * NT);
        const float* c0 = crow + (size_t)r * NT;
        accum_row(cst[r], vm, vc, p0, c0[offL], c0[offR], m0, m3, inv2dt, part);
        vm = vc; vc = p0;
    }

    // ---- block reduce (pde raw sum + pre-weighted edge sum) ----
    part = warp_reduce(part);
    edge = warp_reduce(edge);
    if ((tid & 31) == 0) { s1[tid >> 5] = part; s2[tid >> 5] = edge; }
    __syncthreads();
    if (tid < 32) {
        float vpp = (tid < 16) ? s1[tid] : 0.0f;
        float vee = (tid < 16) ? s2[tid] : 0.0f;
        vpp = warp_reduce(vpp);
        vee = warp_reduce(vee);
        if (tid == 0) {
            g_part[bid] = (double)vpp * W_PDE + (double)vee;
            __threadfence();
            s_old = atomicAdd(&g_count, 1u);
        }
    }
    __syncthreads();

    // ---- last block finishes: plain sum of 296 doubles ----
    if (s_old == NPDE - 1) {
        __threadfence();
        double v = (tid < NPDE) ? g_part[tid] : 0.0;
        v = warp_reduce_d(v);
        __shared__ double sd[16];
        if ((tid & 31) == 0) sd[tid >> 5] = v;
        __syncthreads();
        if (tid < 32) {
            double t2 = (tid < 16) ? sd[tid] : 0.0;
            t2 = warp_reduce_d(t2);
            if (tid == 0) {
                out[0] = (float)t2;
                g_count = 0;   // reset for next graph replay (deterministic)
            }
        }
    }
}

static double solve_depressed_cubic(double Q) {
    const double p = 6.0;             // CHI
    const double q = 6.0 * Q;
    const double sp = sqrt(p);
    double arg = fabs(q) / (2.0 * p * sp / (3.0 * sqrt(3.0)));
    if (arg < 1.0) arg = 1.0;
    const double c = 2.0 * sp * cosh(acosh(arg) / 3.0);
    return (q >= 0.0) ? -c : c;
}

extern "C" void kernel_launch(void* const* d_in, const int* in_sizes, int n_in,
                              void* d_out, int out_size)
{
    const float* V = (const float*)d_in[0];
    float* out = (float*)d_out;

    const double C1 = solve_depressed_cubic((100.0 - 0.0) / 30.0);
    const double C2 = solve_depressed_cubic((100.0 - 300.0) / 30.0);
    const double dL = C2 - C1;
    const float c1f = (float)C1;
    const float c2f = (float)C2;
    const float su_coef  = (float)(30.0 * dL);        // ALPHA_STR * dL
    const float suu_coef = (float)(30.0 * dL * dL);   // ALPHA_STR * dL^2
    const double TAU_MAX = 0.5 * 0.2 * 0.2 * 1.0;     // 0.02
    const double DT_NORM = TAU_MAX / (double)(NT - 1);
    const float inv2dt = (float)(1.0 / (2.0 * DT_NORM));

    loss_kernel<<<NPDE, 512>>>(V, out, c1f, c2f, su_coef, suu_coef, inv2dt);
}